// round 6
// baseline (speedup 1.0000x reference)
#include <cuda_runtime.h>
#include <cstdint>

#define DIM     64
#define KMAX    1024
#define TM      512
#define THREADS 512
#define CAP     32
#define ROWPAD  80            // bytes per padded fp8 row (64 data + 16 pad) -> conflict-free LDS.32

// ---------------- device globals (prep results) ----------------
__device__ float g_c2[KMAX];
__device__ unsigned int g_cmaxU;                   // asuint(max ||c_k||)
__device__ __align__(16) unsigned int g_cbF8[KMAX * (ROWPAD / 4)];  // e4m3(c*2^15), 80B rows

// ---------------- smem layout (byte offsets) ----------------
#define OFF_CB    0            // 1024*80 = 81920
#define OFF_A     81920        // 512*80  = 40960
#define OFF_C2    122880       // 4096
#define OFF_R2    126976       // 2048
#define OFF_CNT   129024       // 2048
#define OFF_CAND  131072       // 512*32*2 = 32768
#define SMEM_DYN  163840

__device__ __forceinline__ unsigned int pack4_e4m3(float a0, float a1, float a2, float a3) {
    unsigned short lo, hi;
    asm("cvt.rn.satfinite.e4m3x2.f32 %0, %1, %2;" : "=h"(lo) : "f"(a1), "f"(a0));
    asm("cvt.rn.satfinite.e4m3x2.f32 %0, %1, %2;" : "=h"(hi) : "f"(a3), "f"(a2));
    return (unsigned int)lo | ((unsigned int)hi << 16);
}

__device__ __forceinline__ void mma_fp8(float& d0, float& d1, float& d2, float& d3,
                                        unsigned int a0, unsigned int a1,
                                        unsigned int a2, unsigned int a3,
                                        unsigned int b0, unsigned int b1) {
    asm volatile(
        "mma.sync.aligned.m16n8k32.row.col.f32.e4m3.e4m3.f32 "
        "{%0,%1,%2,%3}, {%4,%5,%6,%7}, {%8,%9}, {%0,%1,%2,%3};"
        : "+f"(d0), "+f"(d1), "+f"(d2), "+f"(d3)
        : "r"(a0), "r"(a1), "r"(a2), "r"(a3), "r"(b0), "r"(b1));
}

// ---------------- prep: c2 (R1-exact) + fp8 codebook image (scaled 2^15) + Cmax ----------------
__global__ void prep_kernel(const float* __restrict__ cb, int K) {
    int k = blockIdx.x * blockDim.x + threadIdx.x;
    if (k >= K) return;
    const float4* row = reinterpret_cast<const float4*>(cb + (size_t)k * DIM);
    float p0 = 0.f, p1 = 0.f, p2 = 0.f, p3 = 0.f;
    unsigned int* dst = g_cbF8 + (size_t)k * (ROWPAD / 4);
#pragma unroll
    for (int j = 0; j < 16; j++) {
        float4 v = row[j];
        p0 += v.x * v.x;
        p1 += v.y * v.y;
        p2 += v.z * v.z;
        p3 += v.w * v.w;
        const float S = 32768.0f;
        dst[j] = pack4_e4m3(v.x * S, v.y * S, v.z * S, v.w * S);
    }
    dst[16] = dst[17] = dst[18] = dst[19] = 0;   // pad
    float c2 = (p0 + p1) + (p2 + p3);
    g_c2[k] = c2;
    atomicMax(&g_cmaxU, __float_as_uint(sqrtf(c2)));
}

// ---------------- main: two-pass FP8 MMA (min scan, then superset collect) ----------------
__global__ __launch_bounds__(THREADS, 1)
void vq_main(const float* __restrict__ residual,
             const float* __restrict__ cb,
             float* __restrict__ qout,
             float* __restrict__ codes,
             int N, int K, int wq, int wc)
{
    extern __shared__ __align__(16) unsigned char dsm[];

    float*          sC2   = (float*)(dsm + OFF_C2);
    float*          sR2   = (float*)(dsm + OFF_R2);
    int*            sCNT  = (int*)(dsm + OFF_CNT);
    unsigned short* sCand = (unsigned short*)(dsm + OFF_CAND);

    const int tid  = threadIdx.x;
    const int lane = tid & 31;
    const int warp = tid >> 5;
    const int m0   = blockIdx.x * TM;
    const int rows = (N - m0 < TM) ? (N - m0) : TM;
    const int NT   = K >> 3;

    // --- stage codebook fp8 image (identity uint4 copy: 80KB) ---
    {
        const uint4* src = reinterpret_cast<const uint4*>(g_cbF8);
        uint4* dst = reinterpret_cast<uint4*>(dsm + OFF_CB);
        const int n16 = (K * ROWPAD) / 16;
#pragma unroll 5
        for (int i = tid; i < n16; i += THREADS) dst[i] = src[i];
    }
    for (int i = tid; i < K; i += THREADS) sC2[i] = g_c2[i];

    // --- per-row: residual -> fp8 (scale 2^4) padded smem row + exact r2 (R1 pattern) ---
    {
        const int r = tid;
        unsigned int* aRow = reinterpret_cast<unsigned int*>(dsm + OFF_A + r * ROWPAD);
        float r2 = 0.f;
        if (r < rows) {
            const float4* rr = reinterpret_cast<const float4*>(residual + (size_t)(m0 + r) * DIM);
            float p0 = 0.f, p1 = 0.f, p2 = 0.f, p3 = 0.f;
#pragma unroll
            for (int j = 0; j < 16; j++) {
                float4 v = rr[j];
                p0 += v.x * v.x;
                p1 += v.y * v.y;
                p2 += v.z * v.z;
                p3 += v.w * v.w;
                const float S = 16.0f;
                aRow[j] = pack4_e4m3(v.x * S, v.y * S, v.z * S, v.w * S);
            }
            r2 = (p0 + p1) + (p2 + p3);
        } else {
#pragma unroll
            for (int j = 0; j < 16; j++) aRow[j] = 0;
        }
        sR2[r]  = r2;
        sCNT[r] = 0;
    }
    __syncthreads();

    // --- A fragments (resident): 2 m-tiles x 2 k32-chunks x 4 regs ---
    unsigned int A[2][2][4];
#pragma unroll
    for (int mt = 0; mt < 2; mt++) {
        const int g = warp * 32 + mt * 16 + (lane >> 2);
#pragma unroll
        for (int kc = 0; kc < 2; kc++) {
            const unsigned char* base = dsm + OFF_A + g * ROWPAD + kc * 32 + (lane & 3) * 4;
            A[mt][kc][0] = *(const unsigned int*)(base);
            A[mt][kc][1] = *(const unsigned int*)(base + 8 * ROWPAD);
            A[mt][kc][2] = *(const unsigned int*)(base + 16);
            A[mt][kc][3] = *(const unsigned int*)(base + 8 * ROWPAD + 16);
        }
    }

    const unsigned char* cbBase = dsm + OFF_CB + (lane >> 2) * ROWPAD + (lane & 3) * 4;
    const float* c2p = sC2 + ((lane & 3) << 1);
    const float DEQ = -3.814697265625e-06f;   // -2 * 2^-19  (A x16, B x32768)

    // ================= PASS A: per-row min of s~ = c2 - 2*dot =================
    float mA0a = 3.0e38f, mA0b = 3.0e38f, mA1a = 3.0e38f, mA1b = 3.0e38f;
    float mB0a = 3.0e38f, mB0b = 3.0e38f, mB1a = 3.0e38f, mB1b = 3.0e38f;

    unsigned int b0, b1, b2, b3;
    {
        const unsigned char* p = cbBase;
        b0 = *(const unsigned int*)(p);
        b1 = *(const unsigned int*)(p + 16);
        b2 = *(const unsigned int*)(p + 32);
        b3 = *(const unsigned int*)(p + 48);
    }
#pragma unroll 2
    for (int nt = 0; nt < NT; nt++) {
        unsigned int n0, n1, n2, n3;
        {
            const int ntn = (nt + 1 < NT) ? nt + 1 : nt;
            const unsigned char* p = cbBase + ntn * (8 * ROWPAD);
            n0 = *(const unsigned int*)(p);
            n1 = *(const unsigned int*)(p + 16);
            n2 = *(const unsigned int*)(p + 32);
            n3 = *(const unsigned int*)(p + 48);
        }
        const float2 c2v = *reinterpret_cast<const float2*>(c2p + (nt << 3));
#pragma unroll
        for (int mt = 0; mt < 2; mt++) {
            float d0 = 0.f, d1 = 0.f, d2 = 0.f, d3 = 0.f;
            mma_fp8(d0, d1, d2, d3, A[mt][0][0], A[mt][0][1], A[mt][0][2], A[mt][0][3], b0, b1);
            mma_fp8(d0, d1, d2, d3, A[mt][1][0], A[mt][1][1], A[mt][1][2], A[mt][1][3], b2, b3);
            float s0 = __fmaf_rn(d0, DEQ, c2v.x);
            float s1 = __fmaf_rn(d1, DEQ, c2v.y);
            float s2 = __fmaf_rn(d2, DEQ, c2v.x);
            float s3 = __fmaf_rn(d3, DEQ, c2v.y);
            if (mt == 0) {
                mA0a = fminf(mA0a, s0); mA0b = fminf(mA0b, s1);
                mA1a = fminf(mA1a, s2); mA1b = fminf(mA1b, s3);
            } else {
                mB0a = fminf(mB0a, s0); mB0b = fminf(mB0b, s1);
                mB1a = fminf(mB1a, s2); mB1b = fminf(mB1b, s3);
            }
        }
        b0 = n0; b1 = n1; b2 = n2; b3 = n3;
    }

    // --- quad reduce + deterministic fp8 error window -> per-slot limits ---
    const float CmaxC = __uint_as_float(g_cmaxU) * 0.26f;
    float lim[2][2];
    {
        float v00 = fminf(mA0a, mA0b);
        float v01 = fminf(mA1a, mA1b);
        float v10 = fminf(mB0a, mB0b);
        float v11 = fminf(mB1a, mB1b);
        v00 = fminf(v00, __shfl_xor_sync(0xFFFFFFFFu, v00, 1));
        v00 = fminf(v00, __shfl_xor_sync(0xFFFFFFFFu, v00, 2));
        v01 = fminf(v01, __shfl_xor_sync(0xFFFFFFFFu, v01, 1));
        v01 = fminf(v01, __shfl_xor_sync(0xFFFFFFFFu, v01, 2));
        v10 = fminf(v10, __shfl_xor_sync(0xFFFFFFFFu, v10, 1));
        v10 = fminf(v10, __shfl_xor_sync(0xFFFFFFFFu, v10, 2));
        v11 = fminf(v11, __shfl_xor_sync(0xFFFFFFFFu, v11, 1));
        v11 = fminf(v11, __shfl_xor_sync(0xFFFFFFFFu, v11, 2));
        const int rbase = warp * 32 + (lane >> 2);
        lim[0][0] = v00 + (sqrtf(sR2[rbase +  0]) * CmaxC + 1e-3f);
        lim[0][1] = v01 + (sqrtf(sR2[rbase +  8]) * CmaxC + 1e-3f);
        lim[1][0] = v10 + (sqrtf(sR2[rbase + 16]) * CmaxC + 1e-3f);
        lim[1][1] = v11 + (sqrtf(sR2[rbase + 24]) * CmaxC + 1e-3f);
    }

    // ================= PASS B: bitwise replay, collect s~ <= lim =================
    const int rA0 = warp * 32 + (lane >> 2);
    {
        const unsigned char* p = cbBase;
        b0 = *(const unsigned int*)(p);
        b1 = *(const unsigned int*)(p + 16);
        b2 = *(const unsigned int*)(p + 32);
        b3 = *(const unsigned int*)(p + 48);
    }
#pragma unroll 2
    for (int nt = 0; nt < NT; nt++) {
        unsigned int n0, n1, n2, n3;
        {
            const int ntn = (nt + 1 < NT) ? nt + 1 : nt;
            const unsigned char* p = cbBase + ntn * (8 * ROWPAD);
            n0 = *(const unsigned int*)(p);
            n1 = *(const unsigned int*)(p + 16);
            n2 = *(const unsigned int*)(p + 32);
            n3 = *(const unsigned int*)(p + 48);
        }
        const float2 c2v = *reinterpret_cast<const float2*>(c2p + (nt << 3));
        const int colb = (nt << 3) + ((lane & 3) << 1);
#pragma unroll
        for (int mt = 0; mt < 2; mt++) {
            float d0 = 0.f, d1 = 0.f, d2 = 0.f, d3 = 0.f;
            mma_fp8(d0, d1, d2, d3, A[mt][0][0], A[mt][0][1], A[mt][0][2], A[mt][0][3], b0, b1);
            mma_fp8(d0, d1, d2, d3, A[mt][1][0], A[mt][1][1], A[mt][1][2], A[mt][1][3], b2, b3);
            float s0 = __fmaf_rn(d0, DEQ, c2v.x);
            float s1 = __fmaf_rn(d1, DEQ, c2v.y);
            float s2 = __fmaf_rn(d2, DEQ, c2v.x);
            float s3 = __fmaf_rn(d3, DEQ, c2v.y);
            const int rA = rA0 + mt * 16, rB = rA + 8;
            if (s0 <= lim[mt][0]) {
                int c = atomicAdd(&sCNT[rA], 1);
                if (c < CAP) sCand[rA * CAP + c] = (unsigned short)colb;
            }
            if (s1 <= lim[mt][0]) {
                int c = atomicAdd(&sCNT[rA], 1);
                if (c < CAP) sCand[rA * CAP + c] = (unsigned short)(colb + 1);
            }
            if (s2 <= lim[mt][1]) {
                int c = atomicAdd(&sCNT[rB], 1);
                if (c < CAP) sCand[rB * CAP + c] = (unsigned short)colb;
            }
            if (s3 <= lim[mt][1]) {
                int c = atomicAdd(&sCNT[rB], 1);
                if (c < CAP) sCand[rB * CAP + c] = (unsigned short)(colb + 1);
            }
        }
        b0 = n0; b1 = n1; b2 = n2; b3 = n3;
    }
    __syncthreads();

    // ================= exact phase: R1-proven fp32 on candidate set =================
    const int t = tid;
    if (t < rows) {
        const int cn = sCNT[t];
        int bestK;
        if (cn == 1) {
            bestK = sCand[t * CAP];
        } else {
            const float r2 = sR2[t];
            float r[DIM];
            const float4* rr = reinterpret_cast<const float4*>(residual + (size_t)(m0 + t) * DIM);
#pragma unroll
            for (int j = 0; j < 16; j++) {
                float4 v = rr[j];
                r[4 * j + 0] = v.x; r[4 * j + 1] = v.y;
                r[4 * j + 2] = v.z; r[4 * j + 3] = v.w;
            }
            float best = 3.402823466e+38f;
            bestK = 0x7FFFFFFF;
            if (cn <= CAP) {
                for (int i = 0; i < cn; i++) {
                    int k = sCand[t * CAP + i];
                    const float4* c4 = reinterpret_cast<const float4*>(cb + (size_t)k * DIM);
                    float a0 = 0.f;
#pragma unroll
                    for (int j = 0; j < 16; j++) {
                        float4 v = c4[j];
                        a0 += r[4 * j + 0] * v.x;
                        a0 += r[4 * j + 1] * v.y;
                        a0 += r[4 * j + 2] * v.z;
                        a0 += r[4 * j + 3] * v.w;
                    }
                    float d = (r2 + sC2[k]) - 2.0f * a0;
                    if (d < best || (d == best && k < bestK)) { best = d; bestK = k; }
                }
            } else {
                for (int k = 0; k < K; k++) {      // overflow fallback (statistically never)
                    const float4* c4 = reinterpret_cast<const float4*>(cb + (size_t)k * DIM);
                    float a0 = 0.f;
#pragma unroll
                    for (int j = 0; j < 16; j++) {
                        float4 v = c4[j];
                        a0 += r[4 * j + 0] * v.x;
                        a0 += r[4 * j + 1] * v.y;
                        a0 += r[4 * j + 2] * v.z;
                        a0 += r[4 * j + 3] * v.w;
                    }
                    float d = (r2 + sC2[k]) - 2.0f * a0;
                    if (d < best) { best = d; bestK = k; }
                }
            }
        }
        const int n = m0 + t;
        if (wc) codes[n] = (float)bestK;
        if (wq) {
            const float4* brow = reinterpret_cast<const float4*>(cb + (size_t)bestK * DIM);
            float4* qo = reinterpret_cast<float4*>(qout + (size_t)n * DIM);
#pragma unroll
            for (int j = 0; j < 16; j++) qo[j] = brow[j];
        }
    }
}

// ---------------- launch ----------------
extern "C" void kernel_launch(void* const* d_in, const int* in_sizes, int n_in,
                              void* d_out, int out_size)
{
    const float* residual = (const float*)d_in[0];
    const float* cb       = (const float*)d_in[1];
    const int N = in_sizes[0] / DIM;
    const int K = in_sizes[1] / DIM;

    float* out = (float*)d_out;
    int write_q = 0, write_codes = 0;
    float* qout = out;
    float* codes = out;
    if (out_size >= N * DIM + N) {
        write_q = 1; write_codes = 1;
        codes = out + (size_t)N * DIM;
    } else if (out_size >= N * DIM) {
        write_q = 1;
    } else {
        write_codes = 1;
    }

    cudaFuncSetAttribute(vq_main, cudaFuncAttributeMaxDynamicSharedMemorySize, SMEM_DYN);

    prep_kernel<<<(K + 255) / 256, 256>>>(cb, K);

    int blocks = (N + TM - 1) / TM;
    vq_main<<<blocks, THREADS, SMEM_DYN>>>(residual, cb, qout, codes,
                                           N, K, write_q, write_codes);
}

// round 7
// speedup vs baseline: 15.3217x; 15.3217x over previous
#include <cuda_runtime.h>
#include <cuda_bf16.h>
#include <cstdint>

#define DIM     64
#define KMAX    1024
#define TM      512
#define THREADS 512
#define CAP     16

// ---------------- device globals (prep results) ----------------
__device__ float g_c2[KMAX];
__device__ unsigned int g_cmaxU;   // asuint(max ||c_k||), positive-float monotone
// bf16 codebook, 128B rows, 16B-chunk XOR swizzle: chunk_phys = chunk ^ (k&7)
__device__ __align__(16) unsigned short g_cbB[KMAX * DIM];

// ---------------- smem layout (byte offsets) ----------------
#define OFF_CB    0          // 1024*128 = 131072
#define OFF_A     131072     // 512*128  =  65536
#define OFF_C2    196608     // 1024*4   =   4096
#define OFF_R2    200704     // 512*4    =   2048
#define OFF_CNT   202752     // 512*4    =   2048
#define OFF_CAND  204800     // 512*16*2 =  16384
#define SMEM_DYN  221184

__device__ __forceinline__ uint32_t smem_u32(const void* p) {
    uint32_t a;
    asm("{ .reg .u64 t; cvta.to.shared.u64 t, %1; cvt.u32.u64 %0, t; }"
        : "=r"(a) : "l"(p));
    return a;
}

// ---------------- prep: c2 (R1-exact) + swizzled bf16 codebook + Cmax ----------------
__global__ void prep_kernel(const float* __restrict__ cb, int K) {
    int k = blockIdx.x * blockDim.x + threadIdx.x;
    if (k >= K) return;
    const float4* row = reinterpret_cast<const float4*>(cb + (size_t)k * DIM);
    float vals[DIM];
    float p0 = 0.f, p1 = 0.f, p2 = 0.f, p3 = 0.f;
#pragma unroll
    for (int j = 0; j < 16; j += 4) {
        float4 a = row[j + 0];
        float4 b = row[j + 1];
        float4 c = row[j + 2];
        float4 d = row[j + 3];
        p0 += a.x * a.x + a.y * a.y + a.z * a.z + a.w * a.w;
        p1 += b.x * b.x + b.y * b.y + b.z * b.z + b.w * b.w;
        p2 += c.x * c.x + c.y * c.y + c.z * c.z + c.w * c.w;
        p3 += d.x * d.x + d.y * d.y + d.z * d.z + d.w * d.w;
        vals[4*(j+0)+0]=a.x; vals[4*(j+0)+1]=a.y; vals[4*(j+0)+2]=a.z; vals[4*(j+0)+3]=a.w;
        vals[4*(j+1)+0]=b.x; vals[4*(j+1)+1]=b.y; vals[4*(j+1)+2]=b.z; vals[4*(j+1)+3]=b.w;
        vals[4*(j+2)+0]=c.x; vals[4*(j+2)+1]=c.y; vals[4*(j+2)+2]=c.z; vals[4*(j+2)+3]=c.w;
        vals[4*(j+3)+0]=d.x; vals[4*(j+3)+1]=d.y; vals[4*(j+3)+2]=d.z; vals[4*(j+3)+3]=d.w;
    }
    float c2 = (p0 + p1) + (p2 + p3);
    g_c2[k] = c2;
    atomicMax(&g_cmaxU, __float_as_uint(sqrtf(c2)));
#pragma unroll
    for (int c = 0; c < DIM; c++) {
        __nv_bfloat16 h = __float2bfloat16(vals[c]);
        int phys = (c >> 3) ^ (k & 7);               // 16B chunk swizzle
        g_cbB[(size_t)k * DIM + phys * 8 + (c & 7)] = *reinterpret_cast<unsigned short*>(&h);
    }
}

// ---------------- inner-step macros (bq = 8-reg B fragment buffer) ----------------
#define MMA16816(d0, d1, d2, d3, ar, b0r, b1r)                                    \
    asm volatile(                                                                  \
        "mma.sync.aligned.m16n8k16.row.col.f32.bf16.bf16.f32 "                     \
        "{%0,%1,%2,%3}, {%4,%5,%6,%7}, {%8,%9}, {%0,%1,%2,%3};"                    \
        : "+f"(d0), "+f"(d1), "+f"(d2), "+f"(d3)                                   \
        : "r"((ar)[0]), "r"((ar)[1]), "r"((ar)[2]), "r"((ar)[3]),                  \
          "r"(b0r), "r"(b1r))

#define LDSM_X4(bq, off, addr)                                                     \
    asm volatile("ldmatrix.sync.aligned.m8n8.x4.shared.b16 {%0,%1,%2,%3}, [%4];"   \
        : "=r"((bq)[(off)]),   "=r"((bq)[(off)+1]),                                \
          "=r"((bq)[(off)+2]), "=r"((bq)[(off)+3]) : "r"(addr))

// computes the 8 s~ values for one nt; emits 4 independent 2-MMA chains per step
#define COMPUTE_S(bq, ntv)                                                         \
    const float2 c2v = *reinterpret_cast<const float2*>(c2p + ((ntv) << 3));       \
    float s0m0, s1m0, s2m0, s3m0, s0m1, s1m1, s2m1, s3m1;                          \
    {                                                                              \
        float e0 = 0.f, e1 = 0.f, e2 = 0.f, e3 = 0.f;                              \
        float f0 = 0.f, f1 = 0.f, f2 = 0.f, f3 = 0.f;                              \
        float g0 = 0.f, g1 = 0.f, g2 = 0.f, g3 = 0.f;                              \
        float h0 = 0.f, h1 = 0.f, h2 = 0.f, h3 = 0.f;                              \
        MMA16816(e0, e1, e2, e3, a[0][0], (bq)[0], (bq)[1]);                       \
        MMA16816(g0, g1, g2, g3, a[1][0], (bq)[0], (bq)[1]);                       \
        MMA16816(f0, f1, f2, f3, a[0][2], (bq)[4], (bq)[5]);                       \
        MMA16816(h0, h1, h2, h3, a[1][2], (bq)[4], (bq)[5]);                       \
        MMA16816(e0, e1, e2, e3, a[0][1], (bq)[2], (bq)[3]);                       \
        MMA16816(g0, g1, g2, g3, a[1][1], (bq)[2], (bq)[3]);                       \
        MMA16816(f0, f1, f2, f3, a[0][3], (bq)[6], (bq)[7]);                       \
        MMA16816(h0, h1, h2, h3, a[1][3], (bq)[6], (bq)[7]);                       \
        s0m0 = __fmaf_rn(__fadd_rn(e0, f0), -2.0f, c2v.x);                         \
        s1m0 = __fmaf_rn(__fadd_rn(e1, f1), -2.0f, c2v.y);                         \
        s2m0 = __fmaf_rn(__fadd_rn(e2, f2), -2.0f, c2v.x);                         \
        s3m0 = __fmaf_rn(__fadd_rn(e3, f3), -2.0f, c2v.y);                         \
        s0m1 = __fmaf_rn(__fadd_rn(g0, h0), -2.0f, c2v.x);                         \
        s1m1 = __fmaf_rn(__fadd_rn(g1, h1), -2.0f, c2v.y);                         \
        s2m1 = __fmaf_rn(__fadd_rn(g2, h2), -2.0f, c2v.x);                         \
        s3m1 = __fmaf_rn(__fadd_rn(g3, h3), -2.0f, c2v.y);                         \
    }

#define PASSA_STEP(bq, ntv) do {                                                   \
    COMPUTE_S(bq, ntv)                                                             \
    mA0a = fminf(mA0a, s0m0); mA0b = fminf(mA0b, s1m0);                            \
    mA1a = fminf(mA1a, s2m0); mA1b = fminf(mA1b, s3m0);                            \
    mB0a = fminf(mB0a, s0m1); mB0b = fminf(mB0b, s1m1);                            \
    mB1a = fminf(mB1a, s2m1); mB1b = fminf(mB1b, s3m1);                            \
} while (0)

#define APPEND(rr, kk) do {                                                        \
    int c = atomicAdd(&sCNT[(rr)], 1);                                             \
    if (c < CAP) sCand[(rr) * CAP + c] = (unsigned short)(kk);                     \
} while (0)

#define PASSB_STEP(bq, ntv) do {                                                   \
    COMPUTE_S(bq, ntv)                                                             \
    const int colb = ((ntv) << 3) + ((lane & 3) << 1);                             \
    if (fminf(s0m0, s1m0) <= lim[0][0]) {                                          \
        if (s0m0 <= lim[0][0]) APPEND(rA0, colb);                                  \
        if (s1m0 <= lim[0][0]) APPEND(rA0, colb + 1);                              \
    }                                                                              \
    if (fminf(s2m0, s3m0) <= lim[0][1]) {                                          \
        if (s2m0 <= lim[0][1]) APPEND(rA0 + 8, colb);                              \
        if (s3m0 <= lim[0][1]) APPEND(rA0 + 8, colb + 1);                          \
    }                                                                              \
    if (fminf(s0m1, s1m1) <= lim[1][0]) {                                          \
        if (s0m1 <= lim[1][0]) APPEND(rA0 + 16, colb);                             \
        if (s1m1 <= lim[1][0]) APPEND(rA0 + 16, colb + 1);                         \
    }                                                                              \
    if (fminf(s2m1, s3m1) <= lim[1][1]) {                                          \
        if (s2m1 <= lim[1][1]) APPEND(rA0 + 24, colb);                             \
        if (s3m1 <= lim[1][1]) APPEND(rA0 + 24, colb + 1);                         \
    }                                                                              \
} while (0)

// ---------------- main: two-pass HMMA (min, then guaranteed-superset collect) ----------------
__global__ __launch_bounds__(THREADS, 1)
void vq_main(const float* __restrict__ residual,
             const float* __restrict__ cb,
             float* __restrict__ qout,
             float* __restrict__ codes,
             int N, int K, int wq, int wc)
{
    extern __shared__ __align__(16) unsigned char dsm[];
    const uint32_t sb = smem_u32(dsm);

    float*          sC2   = (float*)(dsm + OFF_C2);
    float*          sR2   = (float*)(dsm + OFF_R2);
    int*            sCNT  = (int*)(dsm + OFF_CNT);
    unsigned short* sCand = (unsigned short*)(dsm + OFF_CAND);

    const int tid  = threadIdx.x;
    const int lane = tid & 31;
    const int warp = tid >> 5;
    const int m0   = blockIdx.x * TM;
    const int rows = (N - m0 < TM) ? (N - m0) : TM;
    const int NT   = K >> 3;

    // --- stage codebook image (pre-swizzled, identity uint4 copy) ---
    {
        const uint4* src = reinterpret_cast<const uint4*>(g_cbB);
        uint4* dst = reinterpret_cast<uint4*>(dsm + OFF_CB);
        const int n16 = (K * DIM * 2) / 16;
#pragma unroll 4
        for (int i = tid; i < n16; i += THREADS) dst[i] = src[i];
    }
    for (int i = tid; i < K; i += THREADS) sC2[i] = g_c2[i];

    // --- per-row: residual -> bf16 swizzled smem + exact r2 (R1 pattern) ---
    {
        const int r = tid;
        unsigned int* aU = reinterpret_cast<unsigned int*>(dsm + OFF_A) + r * 32;
        float r2 = 0.f;
        if (r < rows) {
            const float4* rr = reinterpret_cast<const float4*>(residual + (size_t)(m0 + r) * DIM);
            float p0 = 0.f, p1 = 0.f, p2 = 0.f, p3 = 0.f;
#pragma unroll
            for (int j = 0; j < 16; j++) {
                float4 v = rr[j];
                p0 += v.x * v.x;
                p1 += v.y * v.y;
                p2 += v.z * v.z;
                p3 += v.w * v.w;
                __nv_bfloat162 h0 = __floats2bfloat162_rn(v.x, v.y);
                __nv_bfloat162 h1 = __floats2bfloat162_rn(v.z, v.w);
                int j0 = 2 * j, j1 = 2 * j + 1;
                aU[(((j0 >> 2) ^ (r & 7)) << 2) + (j0 & 3)] = *reinterpret_cast<unsigned int*>(&h0);
                aU[(((j1 >> 2) ^ (r & 7)) << 2) + (j1 & 3)] = *reinterpret_cast<unsigned int*>(&h1);
            }
            r2 = (p0 + p1) + (p2 + p3);
        } else {
#pragma unroll
            for (int j = 0; j < 32; j++) aU[j] = 0;
        }
        sR2[r]  = r2;
        sCNT[r] = 0;
    }
    __syncthreads();

    // --- A fragments (resident): 2 m-tiles x 4 k-chunks, swizzled ldmatrix.x4 ---
    uint32_t a[2][4][4];
#pragma unroll
    for (int mt = 0; mt < 2; mt++) {
        const uint32_t rowb = (uint32_t)(warp * 32 + mt * 16 + (lane & 15)) * 128u;
#pragma unroll
        for (int kc = 0; kc < 4; kc++) {
            uint32_t phys = (uint32_t)((2 * kc + (lane >> 4)) ^ (lane & 7));
            uint32_t ad = sb + OFF_A + rowb + (phys << 4);
            asm volatile("ldmatrix.sync.aligned.m8n8.x4.shared.b16 {%0,%1,%2,%3}, [%4];"
                : "=r"(a[mt][kc][0]), "=r"(a[mt][kc][1]),
                  "=r"(a[mt][kc][2]), "=r"(a[mt][kc][3])
                : "r"(ad));
        }
    }

    // --- per-lane B base addresses (swizzled; constant + nt*1024) ---
    const uint32_t bb0 = sb + OFF_CB + (uint32_t)(lane & 7) * 128u
                       + ((uint32_t)(((lane >> 3))     ^ (lane & 7)) << 4);
    const uint32_t bb1 = sb + OFF_CB + (uint32_t)(lane & 7) * 128u
                       + ((uint32_t)((4 + (lane >> 3)) ^ (lane & 7)) << 4);
    const float* c2p = sC2 + ((lane & 3) << 1);

    // ================= PASS A: per-row min of s~ = c2 - 2*dot~ =================
    float mA0a = 3.0e38f, mA0b = 3.0e38f, mA1a = 3.0e38f, mA1b = 3.0e38f; // mt0
    float mB0a = 3.0e38f, mB0b = 3.0e38f, mB1a = 3.0e38f, mB1b = 3.0e38f; // mt1

    {
        uint32_t bc[8], bn[8];
        LDSM_X4(bc, 0, bb0);
        LDSM_X4(bc, 4, bb1);
        for (int nt = 0; nt < NT; nt += 2) {
            LDSM_X4(bn, 0, bb0 + (nt + 1) * 1024);
            LDSM_X4(bn, 4, bb1 + (nt + 1) * 1024);
            PASSA_STEP(bc, nt);
            if (nt + 2 < NT) {
                LDSM_X4(bc, 0, bb0 + (nt + 2) * 1024);
                LDSM_X4(bc, 4, bb1 + (nt + 2) * 1024);
            }
            PASSA_STEP(bn, nt + 1);
        }
    }

    // --- quad reduce + threshold -> per-slot limits (registers, exact) ---
    const float CmaxC = __uint_as_float(g_cmaxU) * 0.018f;
    float lim[2][2];
    {
        float v00 = fminf(mA0a, mA0b);
        float v01 = fminf(mA1a, mA1b);
        float v10 = fminf(mB0a, mB0b);
        float v11 = fminf(mB1a, mB1b);
        v00 = fminf(v00, __shfl_xor_sync(0xFFFFFFFFu, v00, 1));
        v00 = fminf(v00, __shfl_xor_sync(0xFFFFFFFFu, v00, 2));
        v01 = fminf(v01, __shfl_xor_sync(0xFFFFFFFFu, v01, 1));
        v01 = fminf(v01, __shfl_xor_sync(0xFFFFFFFFu, v01, 2));
        v10 = fminf(v10, __shfl_xor_sync(0xFFFFFFFFu, v10, 1));
        v10 = fminf(v10, __shfl_xor_sync(0xFFFFFFFFu, v10, 2));
        v11 = fminf(v11, __shfl_xor_sync(0xFFFFFFFFu, v11, 1));
        v11 = fminf(v11, __shfl_xor_sync(0xFFFFFFFFu, v11, 2));
        const int rbase = warp * 32 + (lane >> 2);
        lim[0][0] = v00 + (sqrtf(sR2[rbase +  0]) * CmaxC + 5e-5f);
        lim[0][1] = v01 + (sqrtf(sR2[rbase +  8]) * CmaxC + 5e-5f);
        lim[1][0] = v10 + (sqrtf(sR2[rbase + 16]) * CmaxC + 5e-5f);
        lim[1][1] = v11 + (sqrtf(sR2[rbase + 24]) * CmaxC + 5e-5f);
    }

    // ================= PASS B: bitwise replay, collect s~ <= lim =================
    const int rA0 = warp * 32 + (lane >> 2);
    {
        uint32_t bc[8], bn[8];
        LDSM_X4(bc, 0, bb0);
        LDSM_X4(bc, 4, bb1);
        for (int nt = 0; nt < NT; nt += 2) {
            LDSM_X4(bn, 0, bb0 + (nt + 1) * 1024);
            LDSM_X4(bn, 4, bb1 + (nt + 1) * 1024);
            PASSB_STEP(bc, nt);
            if (nt + 2 < NT) {
                LDSM_X4(bc, 0, bb0 + (nt + 2) * 1024);
                LDSM_X4(bc, 4, bb1 + (nt + 2) * 1024);
            }
            PASSB_STEP(bn, nt + 1);
        }
    }
    __syncthreads();

    // ================= exact phase: R1-proven fp32 on candidate set =================
    const int t = tid;
    if (t < rows) {
        const int cn = sCNT[t];
        int bestK;
        if (cn == 1) {
            bestK = sCand[t * CAP];          // unique candidate: must be the argmin
        } else {
            const float r2 = sR2[t];
            float r[DIM];
            const float4* rr = reinterpret_cast<const float4*>(residual + (size_t)(m0 + t) * DIM);
#pragma unroll
            for (int j = 0; j < 16; j++) {
                float4 v = rr[j];
                r[4 * j + 0] = v.x; r[4 * j + 1] = v.y;
                r[4 * j + 2] = v.z; r[4 * j + 3] = v.w;
            }
            float best = 3.402823466e+38f;
            bestK = 0x7FFFFFFF;
            if (cn <= CAP) {
                for (int i = 0; i < cn; i++) {
                    int k = sCand[t * CAP + i];
                    const float4* c4 = reinterpret_cast<const float4*>(cb + (size_t)k * DIM);
                    float a0 = 0.f;
#pragma unroll
                    for (int j = 0; j < 16; j++) {
                        float4 v = c4[j];
                        a0 += r[4 * j + 0] * v.x;
                        a0 += r[4 * j + 1] * v.y;
                        a0 += r[4 * j + 2] * v.z;
                        a0 += r[4 * j + 3] * v.w;
                    }
                    float d = (r2 + sC2[k]) - 2.0f * a0;
                    if (d < best || (d == best && k < bestK)) { best = d; bestK = k; }
                }
            } else {
                for (int k = 0; k < K; k++) {      // overflow fallback (statistically never)
                    const float4* c4 = reinterpret_cast<const float4*>(cb + (size_t)k * DIM);
                    float a0 = 0.f;
#pragma unroll
                    for (int j = 0; j < 16; j++) {
                        float4 v = c4[j];
                        a0 += r[4 * j + 0] * v.x;
                        a0 += r[4 * j + 1] * v.y;
                        a0 += r[4 * j + 2] * v.z;
                        a0 += r[4 * j + 3] * v.w;
                    }
                    float d = (r2 + sC2[k]) - 2.0f * a0;
                    if (d < best) { best = d; bestK = k; }
                }
            }
        }
        const int n = m0 + t;
        if (wc) codes[n] = (float)bestK;
        if (wq) {
            const float4* brow = reinterpret_cast<const float4*>(cb + (size_t)bestK * DIM);
            float4* qo = reinterpret_cast<float4*>(qout + (size_t)n * DIM);
#pragma unroll
            for (int j = 0; j < 16; j++) qo[j] = brow[j];
        }
    }
}

// ---------------- launch ----------------
extern "C" void kernel_launch(void* const* d_in, const int* in_sizes, int n_in,
                              void* d_out, int out_size)
{
    const float* residual = (const float*)d_in[0];
    const float* cb       = (const float*)d_in[1];
    const int N = in_sizes[0] / DIM;
    const int K = in_sizes[1] / DIM;

    float* out = (float*)d_out;
    int write_q = 0, write_codes = 0;
    float* qout = out;
    float* codes = out;
    if (out_size >= N * DIM + N) {
        write_q = 1; write_codes = 1;
        codes = out + (size_t)N * DIM;
    } else if (out_size >= N * DIM) {
        write_q = 1;
    } else {
        write_codes = 1;
    }

    cudaFuncSetAttribute(vq_main, cudaFuncAttributeMaxDynamicSharedMemorySize, SMEM_DYN);

    prep_kernel<<<(K + 255) / 256, 256>>>(cb, K);

    int blocks = (N + TM - 1) / TM;
    vq_main<<<blocks, THREADS, SMEM_DYN>>>(residual, cb, qout, codes,
                                           N, K, write_q, write_codes);
}